// round 16
// baseline (speedup 1.0000x reference)
#include <cuda_runtime.h>
#include <mma.h>
#include <cstdint>

using namespace nvcuda;

#define N_NODES 50000
#define D_IN    128
#define D_OUT   64
#define FULLM   0xffffffffu

// h scratch: h[row][c] = g_h4[row*16 + c/4]
__device__ float4 g_h4[N_NODES * (D_OUT / 4)];

// ---------------------------------------------------------------------------
// Kernel 1: h = x @ W via tf32 mma.sync, operands staged in smem. (plain)
// ---------------------------------------------------------------------------
#define XS_LD 132
#define WT_LD 132
#define SMEM_WT_OFF (128 * XS_LD)                       // floats
#define GEMM_SMEM   ((128 * XS_LD + 64 * WT_LD) * 4)    // 101376 B

__global__ __launch_bounds__(256) void gemm_tc_kernel(
    const float* __restrict__ x,
    const float* __restrict__ w,
    float* __restrict__ h,
    int n_nodes)
{
    extern __shared__ float sm[];
    float* xs = sm;                  // [128][XS_LD]
    float* wt = sm + SMEM_WT_OFF;    // [64][WT_LD], wt[n][k]

    const int tid = threadIdx.x;
    const int wid = tid >> 5;
    const int row0 = blockIdx.x * 128;

    #pragma unroll
    for (int i = tid; i < D_IN * D_OUT; i += 256) {
        int k = i >> 6, n = i & 63;
        wt[n * WT_LD + k] = wmma::__float_to_tf32(w[i]);
    }
    {
        const float4* x4 = (const float4*)x;
        #pragma unroll
        for (int i = tid; i < 128 * 32; i += 256) {
            int r = i >> 5, c4 = i & 31;
            if (row0 + r < n_nodes) {
                float4 v = x4[(size_t)(row0 + r) * 32 + c4];
                float* p = xs + r * XS_LD + c4 * 4;
                p[0] = wmma::__float_to_tf32(v.x);
                p[1] = wmma::__float_to_tf32(v.y);
                p[2] = wmma::__float_to_tf32(v.z);
                p[3] = wmma::__float_to_tf32(v.w);
            }
        }
    }
    __syncthreads();

    const int wrow = row0 + wid * 16;
    if (wrow >= n_nodes) return;    // 50000 % 16 == 0

    wmma::fragment<wmma::accumulator, 16, 16, 8, float> c[4];
    #pragma unroll
    for (int n = 0; n < 4; n++) wmma::fill_fragment(c[n], 0.0f);

    const float* a_base = xs + wid * 16 * XS_LD;

    #pragma unroll
    for (int k = 0; k < 16; k++) {
        wmma::fragment<wmma::matrix_a, 16, 16, 8, wmma::precision::tf32, wmma::row_major> a;
        wmma::load_matrix_sync(a, a_base + k * 8, XS_LD);
        #pragma unroll
        for (int n = 0; n < 4; n++) {
            wmma::fragment<wmma::matrix_b, 16, 16, 8, wmma::precision::tf32, wmma::col_major> b;
            wmma::load_matrix_sync(b, wt + (n * 16) * WT_LD + k * 8, WT_LD);
            wmma::mma_sync(c[n], a, b, c[n]);
        }
    }

    float* hp = h + (size_t)wrow * D_OUT;
    #pragma unroll
    for (int n = 0; n < 4; n++)
        wmma::store_matrix_sync(hp + n * 16, c[n], D_OUT, wmma::mem_row_major);
}

// ---------------------------------------------------------------------------
// Kernel 2: out[i][:] = bias. Pure streaming float4 stores, no dependencies.
// ---------------------------------------------------------------------------
__global__ void init_kernel(float4* __restrict__ out4,
                            const float4* __restrict__ bias4, int n_total4)
{
    int i = blockIdx.x * blockDim.x + threadIdx.x;
    if (i < n_total4) out4[i] = __ldg(&bias4[i & 15]);
}

// ---------------------------------------------------------------------------
// Kernel 3: segmented scatter over sorted dst (measured 22.7us). Warp owns
// 32 consecutive edges; lanes load (dst,src,val) coalesced; halves process
// even/odd edges via shfl broadcast; register-accumulate per dst segment;
// flush with red.global.add.v4.f32. out pre-initialized to bias.
// ---------------------------------------------------------------------------
__device__ __forceinline__ void red_add_v4(float* p, float4 a) {
    asm volatile("red.global.add.v4.f32 [%0], {%1, %2, %3, %4};"
                 :: "l"(p), "f"(a.x), "f"(a.y), "f"(a.z), "f"(a.w));
}

__global__ __launch_bounds__(256) void scatter_kernel(
    const float4* __restrict__ h4,
    const int*    __restrict__ src,
    const int*    __restrict__ dst,
    const float*  __restrict__ val,
    float*        __restrict__ out,
    int n_edges)
{
    const int lane = threadIdx.x & 31;
    const int f4   = lane & 15;
    const int half = lane >> 4;
    const int warp = (blockIdx.x * blockDim.x + threadIdx.x) >> 5;
    const int e0   = warp * 32;
    if (e0 >= n_edges) return;
    const int cnt = min(32, n_edges - e0);

    // coalesced edge metadata
    int   dv = 0, sv = 0;
    float vv = 0.f;
    if (lane < cnt) {
        const int e = e0 + lane;
        dv = __ldg(&dst[e]);
        sv = __ldg(&src[e]);
        vv = __ldg(&val[e]);
    }

    int cur = __shfl_sync(FULLM, dv, half);   // dst of this half's first edge
    float4 acc = make_float4(0.f, 0.f, 0.f, 0.f);

    #pragma unroll
    for (int jj = 0; jj < 16; jj++) {
        const int j = (jj << 1) | half;
        const int   dj = __shfl_sync(FULLM, dv, j);
        const int   sj = __shfl_sync(FULLM, sv, j);
        const float vj = __shfl_sync(FULLM, vv, j);
        if (j < cnt) {
            if (dj != cur) {                   // uniform per half-warp
                red_add_v4(out + (size_t)cur * D_OUT + f4 * 4, acc);
                acc = make_float4(0.f, 0.f, 0.f, 0.f);
                cur = dj;
            }
            float4 hv = __ldg(&h4[(size_t)sj * 16 + f4]);
            acc.x += vj * hv.x; acc.y += vj * hv.y;
            acc.z += vj * hv.z; acc.w += vj * hv.w;
        }
    }
    red_add_v4(out + (size_t)cur * D_OUT + f4 * 4, acc);
}

// ---------------------------------------------------------------------------
extern "C" void kernel_launch(void* const* d_in, const int* in_sizes, int n_in,
                              void* d_out, int out_size)
{
    const float* x    = (const float*)d_in[0];   // [N, 128]
    const int*   esrc = (const int*)  d_in[1];   // [E]
    const int*   edst = (const int*)  d_in[2];   // [E]
    const float* eval = (const float*)d_in[3];   // [E]
    const float* w    = (const float*)d_in[4];   // [128, 64]
    const float* bias = (const float*)d_in[5];   // [64]
    float* out = (float*)d_out;                  // [N, 64]

    const int n_nodes = in_sizes[0] / D_IN;
    const int n_edges = in_sizes[1];

    float4* h4;
    cudaGetSymbolAddress((void**)&h4, g_h4);

    // 1) out = bias (independent of gemm; ordered before scatter by stream)
    {
        int n_total4 = n_nodes * 16;
        init_kernel<<<(n_total4 + 255) / 256, 256>>>(
            (float4*)out, (const float4*)bias, n_total4);
    }

    // 2) h = x @ W
    {
        cudaFuncSetAttribute(gemm_tc_kernel,
                             cudaFuncAttributeMaxDynamicSharedMemorySize, GEMM_SMEM);
        int blocks = (n_nodes + 127) / 128;
        gemm_tc_kernel<<<blocks, 256, GEMM_SMEM>>>(x, w, (float*)h4, n_nodes);
    }

    // 3) out += A @ h (segmented scatter, vector reductions at boundaries)
    {
        int warps = (n_edges + 31) / 32;
        int threads = warps * 32;
        scatter_kernel<<<(threads + 255) / 256, 256>>>(
            h4, esrc, edst, eval, out, n_edges);
    }
}